// round 7
// baseline (speedup 1.0000x reference)
#include <cuda_runtime.h>
#include <cuda_bf16.h>
#include <cstdint>

// LogitSeparator: out[b,d,j] = logits[b, start(b,d)+j] for j < len(b,d) else 0
//                 mask[b,d,j] = (j < len) ? 1.0 : 0.0
// start = exclusive cumsum of schemas[b,:] at d; len = schemas[b,d] in [0,256).
// Output layout: [out (B*D*L f32)] ++ [mask (B*D*L f32)]  (verified, rel_err 0).
//
// R7: memset the whole 134MB output on the fast fill path (6.9 TB/s measured),
// then one compact kernel (64 CTAs, one per batch row) writes only live zone
// data: single warp-scan per CTA, 8 threads per d-zone, <=8 float4 iterations.

#define D_DIM 32

__global__ void __launch_bounds__(256)
zone_fill_kernel(const unsigned int* __restrict__ schemas_w,
                 const float* __restrict__ logits,
                 float* __restrict__ out,
                 int n_rows, int L) {
    int b = blockIdx.x;                       // batch row

    __shared__ int s_start[D_DIM], s_len[D_DIM];

    if (threadIdx.x < 32) {
        int lane = threadIdx.x;
        // dtype detect: int64 schemas in [0,256) -> odd 32-bit words all zero
        unsigned int oddw = schemas_w[2 * lane + 1];
        bool is64 = (__ballot_sync(0xffffffffu, oddw != 0u) == 0u);

        int idx = b * D_DIM + lane;
        int v = (int)(is64 ? schemas_w[2 * idx] : schemas_w[idx]);
        int x = v;
        #pragma unroll
        for (int o = 1; o < 32; o <<= 1) {
            int y = __shfl_up_sync(0xffffffffu, x, o);
            if (lane >= o) x += y;
        }
        s_start[lane] = x - v;                // exclusive cumsum
        s_len[lane]   = v;
    }
    __syncthreads();

    const int d    = threadIdx.x >> 3;        // 0..31: zone
    const int sub  = threadIdx.x & 7;         // 0..7: vector slot within zone
    const int start = s_start[d];
    const int len   = s_len[d];
    const int nvec  = (len + 3) >> 2;         // <= 64
    const int row   = b * D_DIM + d;

    const float* __restrict__ lrow = logits + (long long)b * L + start;
    float4* __restrict__ orow = reinterpret_cast<float4*>(out + (long long)row * L);
    float4* __restrict__ mrow = reinterpret_cast<float4*>(
        out + (long long)n_rows * L + (long long)row * L);

    const float4 o4 = make_float4(1.f, 1.f, 1.f, 1.f);

    for (int v = sub; v < nvec; v += 8) {
        int j = v << 2;
        float4 val, mk;
        if (j + 3 < len) {
            val.x = lrow[j + 0];
            val.y = lrow[j + 1];
            val.z = lrow[j + 2];
            val.w = lrow[j + 3];
            mk = o4;
        } else {
            // zone-final vector: zero-pad (memset-consistent; zone never
            // reaches the L boundary since sum(schemas) <= 32*255 < 8192)
            val = make_float4(0.f, 0.f, 0.f, 0.f);
            mk  = val;
            if (j + 0 < len) { val.x = lrow[j + 0]; mk.x = 1.f; }
            if (j + 1 < len) { val.y = lrow[j + 1]; mk.y = 1.f; }
            if (j + 2 < len) { val.z = lrow[j + 2]; mk.z = 1.f; }
            if (j + 3 < len) { val.w = lrow[j + 3]; mk.w = 1.f; }
        }
        orow[v] = val;
        mrow[v] = mk;
    }
}

extern "C" void kernel_launch(void* const* d_in, const int* in_sizes, int n_in,
                              void* d_out, int out_size) {
    const unsigned int* schemas_w = (const unsigned int*)d_in[0];
    const float*        logits    = (const float*)d_in[1];
    float*              out       = (float*)d_out;

    int n_rows = in_sizes[0];             // B*D = 2048
    int B      = n_rows / D_DIM;          // 64
    int L      = in_sizes[1] / B;         // 8192

    // Zero entire output (both halves) on the fast fill path (~6.9 TB/s).
    cudaMemsetAsync(d_out, 0, (size_t)out_size * sizeof(float), 0);

    // Write only live zone data (one CTA per batch row).
    zone_fill_kernel<<<B, 256>>>(schemas_w, logits, out, n_rows, L);
}

// round 8
// speedup vs baseline: 1.1965x; 1.1965x over previous
#include <cuda_runtime.h>
#include <cuda_bf16.h>
#include <cstdint>

// LogitSeparator: out[b,d,j] = logits[b, start(b,d)+j] for j < len(b,d) else 0
//                 mask[b,d,j] = (j < len) ? 1.0 : 0.0
// start = exclusive cumsum of schemas[b,:] at d; len = schemas[b,d] in [0,256).
// Output layout: [out (B*D*L f32)] ++ [mask (B*D*L f32)]  (verified, rel_err 0).
//
// R8: memset whole 134MB output (fill path, ~6.9 TB/s measured), then a
// latency-optimized zone kernel: 2048 CTAs (one per row) x 64 threads,
// warp-redundant scan + shfl broadcast (no smem/barriers), parallel-issued
// meta loads, one vector per thread. Everything L2-hot across graph replays.

#define D_DIM 32

__global__ void __launch_bounds__(64)
zone_fill_kernel(const unsigned int* __restrict__ schemas_w,
                 const float* __restrict__ logits,
                 float* __restrict__ out,
                 int n_rows, int L) {
    const int row  = blockIdx.x;              // b*D + d
    const int b    = row >> 5;                // D_DIM == 32
    const int d    = row & (D_DIM - 1);
    const int lane = threadIdx.x & 31;
    const int idx  = (b << 5) + lane;

    // Parallel-issue: dtype-detect word + int32-candidate value (both always
    // in-bounds: words 1..63 and idx<2048 exist for either dtype).
    unsigned int oddw = schemas_w[2 * lane + 1];
    unsigned int v32  = schemas_w[idx];
    // int64 schemas in [0,256): odd 32-bit words of first 32 elems all zero.
    bool is64 = (__ballot_sync(0xffffffffu, oddw != 0u) == 0u);
    int v = (int)(is64 ? schemas_w[2 * idx] : v32);

    // Warp-redundant inclusive scan (every warp computes it; no smem/bar).
    int x = v;
    #pragma unroll
    for (int o = 1; o < 32; o <<= 1) {
        int y = __shfl_up_sync(0xffffffffu, x, o);
        if (lane >= o) x += y;
    }
    const int start = __shfl_sync(0xffffffffu, x - v, d);
    const int len   = __shfl_sync(0xffffffffu, v, d);

    const int vv = threadIdx.x;               // 0..63: this thread's vector
    const int nvec = (len + 3) >> 2;          // <= 64
    if (vv >= nvec) return;

    const int j = vv << 2;
    const float* __restrict__ lrow = logits + (long long)b * L + start;

    float4 val, mk;
    if (j + 3 < len) {
        val.x = lrow[j + 0];
        val.y = lrow[j + 1];
        val.z = lrow[j + 2];
        val.w = lrow[j + 3];
        mk = make_float4(1.f, 1.f, 1.f, 1.f);
    } else {
        // zone-final vector: zero-pad (memset-consistent; zones never reach
        // the row's L boundary since sum(schemas) <= 32*255 < 8192)
        val = make_float4(0.f, 0.f, 0.f, 0.f);
        mk  = val;
        if (j + 0 < len) { val.x = lrow[j + 0]; mk.x = 1.f; }
        if (j + 1 < len) { val.y = lrow[j + 1]; mk.y = 1.f; }
        if (j + 2 < len) { val.z = lrow[j + 2]; mk.z = 1.f; }
    }

    long long off = (long long)row * L + j;
    *reinterpret_cast<float4*>(out + off) = val;
    *reinterpret_cast<float4*>(out + (long long)n_rows * L + off) = mk;
}

extern "C" void kernel_launch(void* const* d_in, const int* in_sizes, int n_in,
                              void* d_out, int out_size) {
    const unsigned int* schemas_w = (const unsigned int*)d_in[0];
    const float*        logits    = (const float*)d_in[1];
    float*              out       = (float*)d_out;

    int n_rows = in_sizes[0];             // B*D = 2048
    int B      = n_rows / D_DIM;          // 64
    int L      = in_sizes[1] / B;         // 8192

    // Zero entire output (both halves) on the fast fill path (~6.9 TB/s).
    cudaMemsetAsync(d_out, 0, (size_t)out_size * sizeof(float), 0);

    // Write only live zone data (one CTA per row, one float4 per thread).
    zone_fill_kernel<<<n_rows, 64>>>(schemas_w, logits, out, n_rows, L);
}

// round 9
// speedup vs baseline: 1.3099x; 1.0948x over previous
#include <cuda_runtime.h>
#include <cuda_bf16.h>
#include <cstdint>

// LogitSeparator: out[b,d,j] = logits[b, start(b,d)+j] for j < len(b,d) else 0
//                 mask[b,d,j] = (j < len) ? 1.0 : 0.0
// start = exclusive cumsum of schemas[b,:] at d; len = schemas[b,d] in [0,256).
// Output layout: [out (B*D*L f32)] ++ [mask (B*D*L f32)]  (verified, rel_err 0).
//
// R9: single balanced kernel. Grid (n_rows, 2): blockIdx.y picks values-half
// vs mask-half, so 4096 CTAs x 32KB contiguous rows -> 6.92 waves at 4 CTA/SM
// (vs 3.46 waves / 13.5% tail loss in R4). Live data fits in the first 64
// float4 vectors of a row (len <= 255 < 256), so only iteration 0 of the
// store loop carries any branching; iterations 1..3 are unconditional zero
// streams. Warp-redundant scan in warps 0-1 only; no smem, no barriers.

#define D_DIM 32

__global__ void __launch_bounds__(512)
split_fill_kernel(const unsigned int* __restrict__ schemas_w,
                  const float* __restrict__ logits,
                  float* __restrict__ out,
                  int n_rows, int L) {
    const int row  = blockIdx.x;              // b*D + d
    const int half = blockIdx.y;              // 0 = values, 1 = mask
    const int b    = row >> 5;                // D_DIM == 32
    const int d    = row & (D_DIM - 1);
    const int tid  = threadIdx.x;

    // ---- meta (warps 0-1 only, warp-redundant, no smem/barrier) ----
    int start = 0, len = 0;
    if (tid < 64) {
        const int lane = tid & 31;
        const int idx  = (b << 5) + lane;
        // dtype detect: int64 schemas in [0,256) -> odd 32-bit words all zero
        unsigned int oddw = schemas_w[2 * lane + 1];
        unsigned int v32  = schemas_w[idx];
        bool is64 = (__ballot_sync(0xffffffffu, oddw != 0u) == 0u);
        int v = (int)(is64 ? schemas_w[2 * idx] : v32);

        int x = v;
        #pragma unroll
        for (int o = 1; o < 32; o <<= 1) {
            int y = __shfl_up_sync(0xffffffffu, x, o);
            if (lane >= o) x += y;
        }
        start = __shfl_sync(0xffffffffu, x - v, d);
        len   = __shfl_sync(0xffffffffu, v, d);
    }

    float* __restrict__ base =
        out + (half ? (long long)n_rows * L : 0ll) + (long long)row * L;
    float4* __restrict__ vec = reinterpret_cast<float4*>(base);

    const float4 z4 = make_float4(0.f, 0.f, 0.f, 0.f);

    // ---- iteration 0: vectors 0..511 (only tid<64 can be live) ----
    float4 w = z4;
    if (tid < 64) {
        const int j = tid << 2;
        if (half == 0) {
            if (j + 3 < len) {
                const float* __restrict__ lrow = logits + (long long)b * L + start;
                w.x = lrow[j + 0];
                w.y = lrow[j + 1];
                w.z = lrow[j + 2];
                w.w = lrow[j + 3];
            } else if (j < len) {
                const float* __restrict__ lrow = logits + (long long)b * L + start;
                if (j + 0 < len) w.x = lrow[j + 0];
                if (j + 1 < len) w.y = lrow[j + 1];
                if (j + 2 < len) w.z = lrow[j + 2];
            }
        } else {
            if (j + 0 < len) w.x = 1.f;
            if (j + 1 < len) w.y = 1.f;
            if (j + 2 < len) w.z = 1.f;
            if (j + 3 < len) w.w = 1.f;
        }
    }
    vec[tid] = w;

    // ---- iterations 1..: pure zero streaming (branch-free) ----
    const int nvec = L >> 2;                  // 2048
    #pragma unroll 4
    for (int v = tid + 512; v < nvec; v += 512)
        vec[v] = z4;
}

extern "C" void kernel_launch(void* const* d_in, const int* in_sizes, int n_in,
                              void* d_out, int out_size) {
    const unsigned int* schemas_w = (const unsigned int*)d_in[0];
    const float*        logits    = (const float*)d_in[1];
    float*              out       = (float*)d_out;

    int n_rows = in_sizes[0];             // B*D = 2048
    int B      = n_rows / D_DIM;          // 64
    int L      = in_sizes[1] / B;         // 8192

    dim3 grid(n_rows, 2);
    split_fill_kernel<<<grid, 512>>>(schemas_w, logits, out, n_rows, L);
}

// round 10
// speedup vs baseline: 1.3320x; 1.0169x over previous
#include <cuda_runtime.h>
#include <cuda_bf16.h>
#include <cstdint>

// LogitSeparator: out[b,d,j] = logits[b, start(b,d)+j] for j < len(b,d) else 0
//                 mask[b,d,j] = (j < len) ? 1.0 : 0.0
// start = exclusive cumsum of schemas[b,:] at d; len = schemas[b,d] in [0,256).
// Output layout: [out (B*D*L f32)] ++ [mask (B*D*L f32)]  (verified, rel_err 0).
//
// R10: static partition. Live data only ever occupies columns [0,256) of a
// row (len <= 255). So:
//   - SM strip kernel writes columns [0,256) of every row-half (8.4MB,
//     gather + mask logic, latency-bound ~3us).
//   - One pitched cudaMemset2DAsync zeroes columns [256,L) of all 2*n_rows
//     rows (125.8MB on the CE fill path, ~6.9 TB/s measured in R6).
// The two regions are disjoint -> run them CONCURRENTLY as two graph
// branches via event fork/join. Same GPU work every call (deterministic);
// stream/events created lazily once, no device memory allocated.

#define D_DIM 32
#define STRIP 256            // columns covered by the strip kernel

__global__ void __launch_bounds__(128)
strip_kernel(const unsigned int* __restrict__ schemas_w,
             const float* __restrict__ logits,
             float* __restrict__ out,
             int n_rows, int L) {
    const int row  = blockIdx.x;              // b*D + d
    const int b    = row >> 5;                // D_DIM == 32
    const int d    = row & (D_DIM - 1);
    const int lane = threadIdx.x & 31;
    const int idx  = (b << 5) + lane;

    // ---- meta: every warp computes it independently (no smem/barrier) ----
    // dtype detect: int64 schemas in [0,256) -> odd 32-bit words all zero.
    unsigned int oddw = schemas_w[2 * lane + 1];
    unsigned int v32  = schemas_w[idx];
    bool is64 = (__ballot_sync(0xffffffffu, oddw != 0u) == 0u);
    int v = (int)(is64 ? schemas_w[2 * idx] : v32);

    int x = v;
    #pragma unroll
    for (int o = 1; o < 32; o <<= 1) {
        int y = __shfl_up_sync(0xffffffffu, x, o);
        if (lane >= o) x += y;
    }
    const int start = __shfl_sync(0xffffffffu, x - v, d);
    const int len   = __shfl_sync(0xffffffffu, v, d);

    // ---- one float4 per thread: tid<64 -> values, tid>=64 -> mask ----
    const int tid  = threadIdx.x;
    const int half = tid >> 6;                // 0 = values, 1 = mask
    const int j    = (tid & 63) << 2;         // column 0..252

    float4 w = make_float4(0.f, 0.f, 0.f, 0.f);
    if (half == 0) {
        const float* __restrict__ lrow = logits + (long long)b * L + start;
        if (j + 3 < len) {
            w.x = lrow[j + 0];
            w.y = lrow[j + 1];
            w.z = lrow[j + 2];
            w.w = lrow[j + 3];
        } else if (j < len) {
            if (j + 0 < len) w.x = lrow[j + 0];
            if (j + 1 < len) w.y = lrow[j + 1];
            if (j + 2 < len) w.z = lrow[j + 2];
        }
    } else {
        if (j + 0 < len) w.x = 1.f;
        if (j + 1 < len) w.y = 1.f;
        if (j + 2 < len) w.z = 1.f;
        if (j + 3 < len) w.w = 1.f;
    }

    long long off = (half ? (long long)n_rows * L : 0ll) + (long long)row * L + j;
    *reinterpret_cast<float4*>(out + off) = w;
}

static cudaStream_t g_side = nullptr;
static cudaEvent_t  g_fork = nullptr;
static cudaEvent_t  g_join = nullptr;

extern "C" void kernel_launch(void* const* d_in, const int* in_sizes, int n_in,
                              void* d_out, int out_size) {
    const unsigned int* schemas_w = (const unsigned int*)d_in[0];
    const float*        logits    = (const float*)d_in[1];
    float*              out       = (float*)d_out;

    int n_rows = in_sizes[0];             // B*D = 2048
    int B      = n_rows / D_DIM;          // 64
    int L      = in_sizes[1] / B;         // 8192

    if (g_side == nullptr) {
        cudaStreamCreateWithFlags(&g_side, cudaStreamNonBlocking);
        cudaEventCreateWithFlags(&g_fork, cudaEventDisableTiming);
        cudaEventCreateWithFlags(&g_join, cudaEventDisableTiming);
    }

    // Fork: bring side stream into the captured graph.
    cudaEventRecord(g_fork, 0);
    cudaStreamWaitEvent(g_side, g_fork, 0);

    // Branch A (CE): zero columns [STRIP, L) of all 2*n_rows row-halves.
    cudaMemset2DAsync(out + STRIP,
                      (size_t)L * sizeof(float),          // pitch = row bytes
                      0,
                      (size_t)(L - STRIP) * sizeof(float),// width bytes
                      (size_t)(2 * n_rows),               // height
                      g_side);

    // Branch B (SM): live strip, columns [0, STRIP).
    strip_kernel<<<n_rows, 128>>>(schemas_w, logits, out, n_rows, L);

    // Join.
    cudaEventRecord(g_join, g_side);
    cudaStreamWaitEvent(0, g_join, 0);
}